// round 15
// baseline (speedup 1.0000x reference)
#include <cuda_runtime.h>
#include <cuda_bf16.h>

#define BB 128
#define TT 152
#define II 75
#define HH 256
#define LL 16
#define CC 625
#define G4 1024
#define EPSV 1e-5f
#define DD 8
#define GRP 8

// ---------------- device scratch (no allocation allowed) ----------------
// Weights per (l,rank): 256KB = [wi_hi | wi_lo | wh_hi | wh_lo], each 64KB
// section layout (A-fragment direct): [kblk16][warpM8][lane32][16B]
__device__ __align__(128) __nv_bfloat16 d_WA[(size_t)LL * GRP * 131072];
// x / h images (B-fragment direct): per t/slot 128KB = [part2][kblk16][nblk16][lane32][8B]
__device__ __align__(128) __nv_bfloat16 d_xB[(size_t)TT * 65536];
__device__ __align__(128) __nv_bfloat16 d_hB[(size_t)LL * DD * 65536];
__device__ unsigned int d_cnt[LL + 1];

__device__ __forceinline__ float sigm(float x) { return 1.f / (1.f + __expf(-x)); }

__device__ __forceinline__ unsigned int ld_acq(const unsigned int* p) {
    unsigned int v;
    asm volatile("ld.global.acquire.gpu.u32 %0, [%1];" : "=r"(v) : "l"(p));
    return v;
}
__device__ __forceinline__ void arrive_rel(unsigned int* p) {
    asm volatile("red.release.gpu.global.add.u32 [%0], 1;" :: "l"(p) : "memory");
}
__device__ __forceinline__ void cp16(unsigned int sa, const void* g) {
    asm volatile("cp.async.cg.shared.global [%0], [%1], 16;" :: "r"(sa), "l"(g));
}
__device__ __forceinline__ void cp_commit() { asm volatile("cp.async.commit_group;"); }
template <int N>
__device__ __forceinline__ void cp_wait() { asm volatile("cp.async.wait_group %0;" :: "n"(N)); }

__device__ __forceinline__ unsigned int smem_u32(const void* p) {
    unsigned int a;
    asm("{ .reg .u64 t; cvta.to.shared.u64 t, %1; cvt.u32.u64 %0, t; }" : "=r"(a) : "l"(p));
    return a;
}

// classic warp MMA: D(m16n8 f32) += A(m16k16 bf16,row) * B(k16n8 bf16,col)
__device__ __forceinline__ void mma16816(float* d, const unsigned* a, const unsigned* b) {
    asm volatile(
        "mma.sync.aligned.m16n8k16.row.col.f32.bf16.bf16.f32 "
        "{%0,%1,%2,%3}, {%4,%5,%6,%7}, {%8,%9}, {%0,%1,%2,%3};"
        : "+f"(d[0]), "+f"(d[1]), "+f"(d[2]), "+f"(d[3])
        : "r"(a[0]), "r"(a[1]), "r"(a[2]), "r"(a[3]), "r"(b[0]), "r"(b[1]));
}

// ================= pre-pass =================
__global__ void prep_reset() {
    int i = threadIdx.x;
    if (i <= LL) d_cnt[i] = (i == 0) ? 0x40000000u : 0u;
}

// B-fragment byte offset for element (k, b) within one 64KB part image
__host__ __device__ __forceinline__ int boff(int k, int b) {
    return (((k >> 4) * 16 + (b >> 3)) * 32 + (b & 7) * 4 + ((k & 7) >> 1)) * 8
           + ((k >> 3) & 1) * 4 + (k & 1) * 2;
}
// A-fragment byte offset for element (j, k) within one 64KB section
__device__ __forceinline__ int aoff(int j, int k) {
    return (((k >> 4) * 8 + (j >> 4)) * 32 + (j & 7) * 4 + ((k & 7) >> 1)) * 16
           + (((j >> 3) & 1) + 2 * ((k >> 3) & 1)) * 4 + (k & 1) * 2;
}

__global__ void prep_xseq(const float* __restrict__ seq) {
    int t = blockIdx.x, tid = threadIdx.x;
    char* base = (char*)(d_xB + (size_t)t * 65536);
    for (int idx = tid; idx < 32768; idx += 256) {
        int b = idx >> 8, k = idx & 255;
        float v = (k < II) ? seq[(b * TT + t) * II + k] : 0.f;
        __nv_bfloat16 hi = __float2bfloat16(v);
        __nv_bfloat16 lo = __float2bfloat16(v - __bfloat162float(hi));
        int off = boff(k, b);
        *(__nv_bfloat16*)(base + off) = hi;
        *(__nv_bfloat16*)(base + 65536 + off) = lo;
    }
}

__global__ void prep_w(const float* __restrict__ Wih0, const float* __restrict__ Wih,
                       const float* __restrict__ Whh) {
    int l = blockIdx.x, rank = blockIdx.y, tid = threadIdx.x;
    char* base = (char*)d_WA + (size_t)(l * GRP + rank) * 262144;
    for (int idx = tid; idx < 32768; idx += 256) {
        int j = idx >> 8, k = idx & 255;
        int col = ((j & 3) << 8) + rank * 32 + (j >> 2);
        float vi;
        if (l == 0) vi = (k < II) ? Wih0[k * G4 + col] : 0.f;
        else        vi = Wih[((size_t)(l - 1) * HH + k) * G4 + col];
        float vh = Whh[((size_t)l * HH + k) * G4 + col];
        int off = aoff(j, k);
        __nv_bfloat16 h1 = __float2bfloat16(vi);
        *(__nv_bfloat16*)(base + off) = h1;
        *(__nv_bfloat16*)(base + 65536 + off) = __float2bfloat16(vi - __bfloat162float(h1));
        __nv_bfloat16 h2 = __float2bfloat16(vh);
        *(__nv_bfloat16*)(base + 131072 + off) = h2;
        *(__nv_bfloat16*)(base + 196608 + off) = __float2bfloat16(vh - __bfloat162float(h2));
    }
}

// ================= wavefront kernel =================
#define P_WI 0
#define P_WH 65536
#define P_STR 131072
#define STRB 24576
#define P_SG  P_STR                    // 67584B, aliases drained stream bufs
#define P_RED (P_STR + 3 * STRB)       // 204800, 8192B (dedicated — no alias)
#define P_PRM (P_RED + 8192)           // 212992, 2304B
#define SMEM_TOT (P_PRM + 2304)        // 215296

__launch_bounds__(1024, 1) __global__ void wave_kernel(
    const float* __restrict__ gih, const float* __restrict__ bih,
    const float* __restrict__ ghh, const float* __restrict__ bhh,
    const float* __restrict__ bias,
    const float* __restrict__ gc,  const float* __restrict__ bc)
{
    extern __shared__ char sm[];
    const unsigned int smb = smem_u32(sm);
    const int tid = threadIdx.x, lane = tid & 31, w = tid >> 5;
    const int wm = w & 7, wn = w >> 3;          // wm: row-block, wn: batch quarter
    const int l = blockIdx.x >> 3, rank = blockIdx.x & 7;

    const char* wab = (const char*)d_WA + (size_t)(l * GRP + rank) * 262144;
    // persistent hi-part weights -> SMEM (1024 threads)
    for (int i = 0; i < 4; i++)
        cp16(smb + P_WI + (tid + i * 1024) * 16, wab + (tid + i * 1024) * 16);
    for (int i = 0; i < 4; i++)
        cp16(smb + P_WH + (tid + i * 1024) * 16, wab + 131072 + (tid + i * 1024) * 16);
    cp_commit();

    // static per-column params -> SMEM
    float* prm = (float*)(sm + P_PRM);
    if (tid < 128) {
        int colg = ((tid & 3) << 8) + rank * 32 + (tid >> 2);
        prm[tid]       = gih[l * G4 + colg];
        prm[128 + tid] = bih[l * G4 + colg] + bias[l * G4 + colg];
        prm[256 + tid] = ghh[l * G4 + colg];
        prm[384 + tid] = bhh[l * G4 + colg];
    } else if (tid < 160) {
        int hcg = tid - 128;
        prm[512 + hcg] = gc[l * HH + rank * 32 + hcg];
        prm[544 + hcg] = bc[l * HH + rank * 32 + hcg];
    }
    cp_wait<0>(); __syncthreads();

    float* red = (float*)(sm + P_RED);
    float* sg  = (float*)(sm + P_SG);
    char* hst  = sm + P_SG;   // alias (h staging after sg reads done)

    char* myring = (char*)d_hB + (size_t)l * DD * 131072;
    const char* xring = (l == 0) ? (const char*)d_xB
                                 : (const char*)d_hB + (size_t)(l - 1) * DD * 131072;

    const int hc = w;                   // epilogue: warp <-> h-column
    float cr[4];
#pragma unroll
    for (int i = 0; i < 4; i++) cr[i] = 0.f;

    for (int t = 0; t < TT; t++) {
        // parallel step-start waits (3 independent L2 round trips)
        if (tid == 0 && l < LL - 1 && t >= DD)
            while (ld_acq(&d_cnt[l + 2]) < (unsigned)(GRP * (t - DD + 1))) {}
        if (tid == 1 && t > 0)
            while (ld_acq(&d_cnt[l + 1]) < (unsigned)(GRP * t)) {}
        if (tid == 2 && l > 0)
            while (ld_acq(&d_cnt[l]) < (unsigned)(GRP * (t + 1))) {}
        __syncthreads();

        const char* xb = xring + (size_t)((l == 0) ? t : (t & 7)) * 131072;
        const char* hb = myring + (size_t)((t - 1) & 7) * 131072;

#define STREAM(kc) do { unsigned int sb_ = smb + P_STR + ((kc) % 3) * STRB;           \
        int t2_ = tid & 255;                                                          \
        int sec_ = tid >> 8;                                                          \
        const char* s0_ = (sec_ == 0) ? (wab + 65536  + (kc) * 4096)                  \
                        : (sec_ == 1) ? (wab + 196608 + (kc) * 4096)                  \
                        : (sec_ == 2) ? (xb + (kc) * 4096)                            \
                                      : (xb + 65536 + (kc) * 4096);                   \
        cp16(sb_ + sec_ * 4096 + t2_ * 16, s0_ + t2_ * 16);                           \
        if (t > 0 && tid < 512)                                                       \
            cp16(sb_ + 16384 + sec_ * 4096 + t2_ * 16,                                \
                 ((sec_ ? hb + 65536 : hb) + (kc) * 4096) + t2_ * 16);                \
        cp_commit(); } while (0)

        float wi[16], wh[16];
#pragma unroll
        for (int i = 0; i < 16; i++) { wi[i] = 0.f; wh[i] = 0.f; }

        STREAM(0); STREAM(1);
#pragma unroll 1
        for (int kc = 0; kc < 16; kc++) {
            if (kc < 15) cp_wait<1>(); else cp_wait<0>();
            __syncthreads();
            if (kc < 14) STREAM(kc + 2);
            const char* sbp = sm + P_STR + (kc % 3) * STRB;
            uint4 aWiH = *(const uint4*)(sm + P_WI + ((kc * 8 + wm) * 32 + lane) * 16);
            uint4 aWhH = *(const uint4*)(sm + P_WH + ((kc * 8 + wm) * 32 + lane) * 16);
            uint4 aWiL = *(const uint4*)(sbp + (wm * 32 + lane) * 16);
            uint4 aWhL = *(const uint4*)(sbp + 4096 + (wm * 32 + lane) * 16);
            bool doWi = (l > 0) || (kc < 5);
#pragma unroll
            for (int nb = 0; nb < 4; nb++) {
                int nblk = wn * 4 + nb;
                if (doWi) {
                    uint2 bXH = *(const uint2*)(sbp + 8192 + (nblk * 32 + lane) * 8);
                    uint2 bXL = *(const uint2*)(sbp + 12288 + (nblk * 32 + lane) * 8);
                    mma16816(wi + nb * 4, &aWiH.x, &bXH.x);
                    mma16816(wi + nb * 4, &aWiH.x, &bXL.x);
                    mma16816(wi + nb * 4, &aWiL.x, &bXH.x);
                }
                if (t > 0) {
                    uint2 bHH = *(const uint2*)(sbp + 16384 + (nblk * 32 + lane) * 8);
                    uint2 bHL = *(const uint2*)(sbp + 20480 + (nblk * 32 + lane) * 8);
                    mma16816(wh + nb * 4, &aWhH.x, &bHH.x);
                    mma16816(wh + nb * 4, &aWhH.x, &bHL.x);
                    mma16816(wh + nb * 4, &aWhL.x, &bHH.x);
                }
            }
        }
#undef STREAM

        // ---- per-warp partial BN stats over this warp's 32 batches ----
        float sl = 0, ql = 0, sh = 0, qh = 0;   // wi side, rows lo/hi
        float tl = 0, rl = 0, th = 0, rh = 0;   // wh side
#pragma unroll
        for (int nb = 0; nb < 4; nb++) {
            sl += wi[nb*4+0] + wi[nb*4+1];
            ql += wi[nb*4+0]*wi[nb*4+0] + wi[nb*4+1]*wi[nb*4+1];
            sh += wi[nb*4+2] + wi[nb*4+3];
            qh += wi[nb*4+2]*wi[nb*4+2] + wi[nb*4+3]*wi[nb*4+3];
            tl += wh[nb*4+0] + wh[nb*4+1];
            rl += wh[nb*4+0]*wh[nb*4+0] + wh[nb*4+1]*wh[nb*4+1];
            th += wh[nb*4+2] + wh[nb*4+3];
            rh += wh[nb*4+2]*wh[nb*4+2] + wh[nb*4+3]*wh[nb*4+3];
        }
#pragma unroll
        for (int o = 1; o <= 2; o <<= 1) {
            sl += __shfl_xor_sync(0xffffffffu, sl, o);
            ql += __shfl_xor_sync(0xffffffffu, ql, o);
            sh += __shfl_xor_sync(0xffffffffu, sh, o);
            qh += __shfl_xor_sync(0xffffffffu, qh, o);
            tl += __shfl_xor_sync(0xffffffffu, tl, o);
            rl += __shfl_xor_sync(0xffffffffu, rl, o);
            th += __shfl_xor_sync(0xffffffffu, th, o);
            rh += __shfl_xor_sync(0xffffffffu, rh, o);
        }
        if ((lane & 3) == 0) {
            float* rp = red + (w * 8 + (lane >> 2)) * 8;
            rp[0] = sl; rp[1] = ql; rp[2] = sh; rp[3] = qh;
            rp[4] = tl; rp[5] = rl; rp[6] = th; rp[7] = rh;
        }
        __syncthreads();

        // ---- combine 4 batch-quarters, per-row BN coefficients ----
        float ai_lo, ai_hi, ah_lo, ah_hi, bs_lo, bs_hi;
        {
            int r = lane >> 2;
            float Sl = 0, Ql = 0, Sh = 0, Qh = 0, Tl = 0, Rl = 0, Th = 0, Rh = 0;
#pragma unroll
            for (int q = 0; q < 4; q++) {
                const float* rp = red + ((q * 8 + wm) * 8 + r) * 8;
                Sl += rp[0]; Ql += rp[1]; Sh += rp[2]; Qh += rp[3];
                Tl += rp[4]; Rl += rp[5]; Th += rp[6]; Rh += rp[7];
            }
            int jlo = wm * 16 + r, jhi = jlo + 8;
            float m = Sl * (1.f/128.f);
            ai_lo = prm[jlo] * rsqrtf(Ql * (1.f/128.f) - m * m + EPSV);
            bs_lo = prm[128 + jlo] - m * ai_lo;
            m = Sh * (1.f/128.f);
            ai_hi = prm[jhi] * rsqrtf(Qh * (1.f/128.f) - m * m + EPSV);
            bs_hi = prm[128 + jhi] - m * ai_hi;
            if (t > 0) {
                m = Tl * (1.f/128.f);
                ah_lo = prm[256 + jlo] * rsqrtf(Rl * (1.f/128.f) - m * m + EPSV);
                bs_lo += prm[384 + jlo] - m * ah_lo;
                m = Th * (1.f/128.f);
                ah_hi = prm[256 + jhi] * rsqrtf(Rh * (1.f/128.f) - m * m + EPSV);
                bs_hi += prm[384 + jhi] - m * ah_hi;
            } else {
                ah_lo = 0.f; ah_hi = 0.f;
                bs_lo += prm[384 + jlo]; bs_hi += prm[384 + jhi];
            }
        }

        // ---- s -> SMEM (all warps done with stream bufs: sg alias safe) ----
        {
            const int c2 = 2 * (lane & 3);
            const int jl = wm * 16 + (lane >> 2);
#pragma unroll
            for (int nb = 0; nb < 4; nb++) {
                int bb = wn * 32 + nb * 8 + c2;
                sg[(bb+0) * 132 + jl]     = ai_lo * wi[nb*4+0] + ah_lo * wh[nb*4+0] + bs_lo;
                sg[(bb+1) * 132 + jl]     = ai_lo * wi[nb*4+1] + ah_lo * wh[nb*4+1] + bs_lo;
                sg[(bb+0) * 132 + jl + 8] = ai_hi * wi[nb*4+2] + ah_hi * wh[nb*4+2] + bs_hi;
                sg[(bb+1) * 132 + jl + 8] = ai_hi * wi[nb*4+3] + ah_hi * wh[nb*4+3] + bs_hi;
            }
        }
        __syncthreads();

        // ---- gates: warp = hc, lane = batch quarter-column; 4 batches each ----
        float og[4];
#pragma unroll
        for (int i = 0; i < 4; i++) {
            float4 sv = *(const float4*)&sg[(i * 32 + lane) * 132 + hc * 4];
            float fg = sigm(sv.x), ig = sigm(sv.y);
            og[i] = sigm(sv.z);
            cr[i] = fg * cr[i] + ig * tanhf(sv.w);
        }

        // ---- BN(c): full-warp reduction (warp owns hc completely) ----
        float cs = 0.f, cq = 0.f;
#pragma unroll
        for (int i = 0; i < 4; i++) { cs += cr[i]; cq += cr[i] * cr[i]; }
#pragma unroll
        for (int o = 1; o <= 16; o <<= 1) {
            cs += __shfl_xor_sync(0xffffffffu, cs, o);
            cq += __shfl_xor_sync(0xffffffffu, cq, o);
        }
        float mc = cs * (1.f/128.f);
        float vc = cq * (1.f/128.f) - mc * mc;
        float rc = rsqrtf(vc + EPSV);
        float ac = prm[512 + hc] * rc, bc_ = prm[544 + hc] - mc * ac;
        __syncthreads();   // sg reads done -> reuse as h staging

        // ---- h, bf16 hi/lo, stage in fragment layout ----
#pragma unroll
        for (int i = 0; i < 4; i++) {
            float h = og[i] * tanhf(ac * cr[i] + bc_);
            __nv_bfloat16 hhi = __float2bfloat16(h);
            __nv_bfloat16 hlo = __float2bfloat16(h - __bfloat162float(hhi));
            int off = ((hc >> 4) * 4096)
                    + ((i * 4 + (lane >> 3)) * 256)
                    + ((lane & 7) * 32) + (((hc & 7) >> 1) * 8)
                    + (((hc >> 3) & 1) * 4) + ((hc & 1) * 2);
            *(__nv_bfloat16*)(hst + off) = hhi;
            *(__nv_bfloat16*)(hst + 8192 + off) = hlo;
        }
        __syncthreads();
        {
            char* slot = myring + (size_t)(t & 7) * 131072;
            int part = tid >> 9, r = tid & 511;
            int kbl = r >> 8, rest = r & 255;
            *(uint4*)(slot + part * 65536 + (rank * 2 + kbl) * 4096 + rest * 16)
                = *(const uint4*)(hst + part * 8192 + kbl * 4096 + rest * 16);
        }
        __threadfence();
        __syncthreads();
        if (tid == 0) arrive_rel(&d_cnt[l + 1]);
    }
}

// ================= final head =================
__launch_bounds__(256) __global__ void final_kernel(
    const float* __restrict__ Wlin, const float* __restrict__ blin,
    float* __restrict__ out)
{
    __shared__ float xr[256];
    __shared__ float lg[CC];
    __shared__ float rbuf[8];
    const char* img = (const char*)d_hB
        + (size_t)((LL - 1) * DD + ((TT - 1) & 7)) * 131072;
    int tid = threadIdx.x, warp = tid >> 5, lane = tid & 31;
    int b = blockIdx.x;
    {
        int off = boff(tid, b);
        float hi = __bfloat162float(*(const __nv_bfloat16*)(img + off));
        float lo = __bfloat162float(*(const __nv_bfloat16*)(img + 65536 + off));
        xr[tid] = hi + lo;
    }
    __syncthreads();

    float lmax = -1e30f;
    for (int cidx = tid; cidx < CC; cidx += 256) {
        float a = blin[cidx];
#pragma unroll 4
        for (int k = 0; k < 256; k++) a += xr[k] * Wlin[k * CC + cidx];
        lg[cidx] = a;
        lmax = fmaxf(lmax, a);
    }
#pragma unroll
    for (int o = 16; o; o >>= 1) lmax = fmaxf(lmax, __shfl_xor_sync(0xffffffffu, lmax, o));
    if (lane == 0) rbuf[warp] = lmax;
    __syncthreads();
    float M = rbuf[0];
#pragma unroll
    for (int w2 = 1; w2 < 8; w2++) M = fmaxf(M, rbuf[w2]);
    __syncthreads();
    float lsum = 0.f;
    for (int cidx = tid; cidx < CC; cidx += 256) {
        float e = __expf(lg[cidx] - M);
        lg[cidx] = e;
        lsum += e;
    }
#pragma unroll
    for (int o = 16; o; o >>= 1) lsum += __shfl_xor_sync(0xffffffffu, lsum, o);
    if (lane == 0) rbuf[warp] = lsum;
    __syncthreads();
    float S = 0.f;
#pragma unroll
    for (int w2 = 0; w2 < 8; w2++) S += rbuf[w2];
    float inv = 1.f / S;
    for (int cidx = tid; cidx < CC; cidx += 256)
        out[b * CC + cidx] = lg[cidx] * inv;
}

// ================= launch =================
extern "C" void kernel_launch(void* const* d_in, const int* in_sizes, int n_in,
                              void* d_out, int out_size)
{
    const float* seq  = (const float*)d_in[0];
    const float* Wih0 = (const float*)d_in[1];
    const float* Wih  = (const float*)d_in[2];
    const float* Whh  = (const float*)d_in[3];
    const float* bias = (const float*)d_in[4];
    const float* gih  = (const float*)d_in[5];
    const float* bih  = (const float*)d_in[6];
    const float* ghh  = (const float*)d_in[7];
    const float* bhh  = (const float*)d_in[8];
    const float* gc   = (const float*)d_in[9];
    const float* bc   = (const float*)d_in[10];
    const float* Wlin = (const float*)d_in[11];
    const float* blin = (const float*)d_in[12];
    float* out = (float*)d_out;

    cudaFuncSetAttribute((const void*)wave_kernel,
                         cudaFuncAttributeMaxDynamicSharedMemorySize, SMEM_TOT);

    prep_reset<<<1, 32>>>();
    prep_xseq<<<TT, 256>>>(seq);
    prep_w<<<dim3(LL, GRP), 256>>>(Wih0, Wih, Whh);
    wave_kernel<<<LL * GRP, 1024, SMEM_TOT>>>(gih, bih, ghh, bhh, bias, gc, bc);
    final_kernel<<<BB, 256>>>(Wlin, blin, out);
}

// round 17
// speedup vs baseline: 1.2325x; 1.2325x over previous
#include <cuda_runtime.h>
#include <cuda_bf16.h>

#define BB 128
#define TT 152
#define II 75
#define HH 256
#define LL 16
#define CC 625
#define G4 1024
#define EPSV 1e-5f
#define DD 8
#define GRP 8

// ---------------- device scratch (no allocation allowed) ----------------
// Weights per (l,rank): 256KB = [wi_hi | wi_lo | wh_hi | wh_lo], each 64KB
// section layout (A-fragment direct): [kblk16][warpM8][lane32][16B]
__device__ __align__(128) __nv_bfloat16 d_WA[(size_t)LL * GRP * 131072];
// x / h images (B-fragment direct): per t/slot 128KB = [part2][kblk16][nblk16][lane32][8B]
__device__ __align__(128) __nv_bfloat16 d_xB[(size_t)TT * 65536];
__device__ __align__(128) __nv_bfloat16 d_hB[(size_t)LL * DD * 65536];
__device__ unsigned int d_cnt[LL + 1];

// fast activations (err ~1e-6, well under the 1e-3 gate)
__device__ __forceinline__ float fsigm(float x) {
    return __fdividef(1.f, 1.f + __expf(-x));
}
__device__ __forceinline__ float ftanh(float x) {
    x = fminf(fmaxf(x, -20.f), 20.f);
    float e = __expf(2.f * x);
    return __fdividef(e - 1.f, e + 1.f);
}

__device__ __forceinline__ unsigned int ld_acq(const unsigned int* p) {
    unsigned int v;
    asm volatile("ld.global.acquire.gpu.u32 %0, [%1];" : "=r"(v) : "l"(p));
    return v;
}
__device__ __forceinline__ void arrive_rel(unsigned int* p) {
    asm volatile("red.release.gpu.global.add.u32 [%0], 1;" :: "l"(p) : "memory");
}
__device__ __forceinline__ void cp16(unsigned int sa, const void* g) {
    asm volatile("cp.async.cg.shared.global [%0], [%1], 16;" :: "r"(sa), "l"(g));
}
__device__ __forceinline__ void cp_commit() { asm volatile("cp.async.commit_group;"); }
template <int N>
__device__ __forceinline__ void cp_wait() { asm volatile("cp.async.wait_group %0;" :: "n"(N)); }

__device__ __forceinline__ unsigned int smem_u32(const void* p) {
    unsigned int a;
    asm("{ .reg .u64 t; cvta.to.shared.u64 t, %1; cvt.u32.u64 %0, t; }" : "=r"(a) : "l"(p));
    return a;
}

// classic warp MMA: D(m16n8 f32) += A(m16k16 bf16,row) * B(k16n8 bf16,col)
__device__ __forceinline__ void mma16816(float* d, const unsigned* a, const unsigned* b) {
    asm volatile(
        "mma.sync.aligned.m16n8k16.row.col.f32.bf16.bf16.f32 "
        "{%0,%1,%2,%3}, {%4,%5,%6,%7}, {%8,%9}, {%0,%1,%2,%3};"
        : "+f"(d[0]), "+f"(d[1]), "+f"(d[2]), "+f"(d[3])
        : "r"(a[0]), "r"(a[1]), "r"(a[2]), "r"(a[3]), "r"(b[0]), "r"(b[1]));
}

// ================= pre-pass =================
__global__ void prep_reset() {
    int i = threadIdx.x;
    if (i <= LL) d_cnt[i] = (i == 0) ? 0x40000000u : 0u;
}

// B-fragment byte offset for element (k, b) within one 64KB part image
__host__ __device__ __forceinline__ int boff(int k, int b) {
    return (((k >> 4) * 16 + (b >> 3)) * 32 + (b & 7) * 4 + ((k & 7) >> 1)) * 8
           + ((k >> 3) & 1) * 4 + (k & 1) * 2;
}
// A-fragment byte offset for element (j, k) within one 64KB section
__device__ __forceinline__ int aoff(int j, int k) {
    return (((k >> 4) * 8 + (j >> 4)) * 32 + (j & 7) * 4 + ((k & 7) >> 1)) * 16
           + (((j >> 3) & 1) + 2 * ((k >> 3) & 1)) * 4 + (k & 1) * 2;
}

__global__ void prep_xseq(const float* __restrict__ seq) {
    int t = blockIdx.x, tid = threadIdx.x;
    char* base = (char*)(d_xB + (size_t)t * 65536);
    for (int idx = tid; idx < 32768; idx += 256) {
        int b = idx >> 8, k = idx & 255;
        float v = (k < II) ? seq[(b * TT + t) * II + k] : 0.f;
        __nv_bfloat16 hi = __float2bfloat16(v);
        __nv_bfloat16 lo = __float2bfloat16(v - __bfloat162float(hi));
        int off = boff(k, b);
        *(__nv_bfloat16*)(base + off) = hi;
        *(__nv_bfloat16*)(base + 65536 + off) = lo;
    }
}

__global__ void prep_w(const float* __restrict__ Wih0, const float* __restrict__ Wih,
                       const float* __restrict__ Whh) {
    int l = blockIdx.x, rank = blockIdx.y, tid = threadIdx.x;
    char* base = (char*)d_WA + (size_t)(l * GRP + rank) * 262144;
    for (int idx = tid; idx < 32768; idx += 256) {
        int j = idx >> 8, k = idx & 255;
        int col = ((j & 3) << 8) + rank * 32 + (j >> 2);
        float vi;
        if (l == 0) vi = (k < II) ? Wih0[k * G4 + col] : 0.f;
        else        vi = Wih[((size_t)(l - 1) * HH + k) * G4 + col];
        float vh = Whh[((size_t)l * HH + k) * G4 + col];
        int off = aoff(j, k);
        __nv_bfloat16 h1 = __float2bfloat16(vi);
        *(__nv_bfloat16*)(base + off) = h1;
        *(__nv_bfloat16*)(base + 65536 + off) = __float2bfloat16(vi - __bfloat162float(h1));
        __nv_bfloat16 h2 = __float2bfloat16(vh);
        *(__nv_bfloat16*)(base + 131072 + off) = h2;
        *(__nv_bfloat16*)(base + 196608 + off) = __float2bfloat16(vh - __bfloat162float(h2));
    }
}

// ================= wavefront kernel =================
#define P_WI 0
#define P_WH 65536
#define P_STR 131072
#define STRB 24576
#define P_SG  P_STR                    // 67584B, aliases all 3 stream bufs (post-loop only)
#define P_RED (P_STR + 3 * STRB)       // 204800, 8192B DEDICATED (no alias: fixes latent race)
#define P_PRM (P_RED + 8192)           // 212992, 2304B
#define SMEM_TOT (P_PRM + 2304)        // 215296

__launch_bounds__(512, 1) __global__ void wave_kernel(
    const float* __restrict__ gih, const float* __restrict__ bih,
    const float* __restrict__ ghh, const float* __restrict__ bhh,
    const float* __restrict__ bias,
    const float* __restrict__ gc,  const float* __restrict__ bc)
{
    extern __shared__ char sm[];
    const unsigned int smb = smem_u32(sm);
    const int tid = threadIdx.x, lane = tid & 31, w = tid >> 5;
    const int wm = w & 7, wn = w >> 3;
    const int l = blockIdx.x >> 3, rank = blockIdx.x & 7;

    const char* wab = (const char*)d_WA + (size_t)(l * GRP + rank) * 262144;
    // persistent hi-part weights -> SMEM (512 threads)
    for (int i = 0; i < 8; i++)
        cp16(smb + P_WI + (tid + i * 512) * 16, wab + (tid + i * 512) * 16);
    for (int i = 0; i < 8; i++)
        cp16(smb + P_WH + (tid + i * 512) * 16, wab + 131072 + (tid + i * 512) * 16);
    cp_commit();

    // static per-column params -> SMEM
    float* prm = (float*)(sm + P_PRM);
    if (tid < 128) {
        int colg = ((tid & 3) << 8) + rank * 32 + (tid >> 2);
        prm[tid]       = gih[l * G4 + colg];
        prm[128 + tid] = bih[l * G4 + colg] + bias[l * G4 + colg];
        prm[256 + tid] = ghh[l * G4 + colg];
        prm[384 + tid] = bhh[l * G4 + colg];
    } else if (tid < 160) {
        int hcg = tid - 128;
        prm[512 + hcg] = gc[l * HH + rank * 32 + hcg];
        prm[544 + hcg] = bc[l * HH + rank * 32 + hcg];
    }
    cp_wait<0>(); __syncthreads();

    const int hc = tid >> 4, bq = tid & 15;

    float* red = (float*)(sm + P_RED);
    float* sg  = (float*)(sm + P_SG);
    char* hst  = sm + P_SG;   // alias (h staging after sg reads done)

    char* myring = (char*)d_hB + (size_t)l * DD * 131072;
    const char* xring = (l == 0) ? (const char*)d_xB
                                 : (const char*)d_hB + (size_t)(l - 1) * DD * 131072;

    float cr[8];
#pragma unroll
    for (int i = 0; i < 8; i++) cr[i] = 0.f;

    for (int t = 0; t < TT; t++) {
        // parallel step-start waits (3 independent L2 round trips)
        if (tid == 0 && l < LL - 1 && t >= DD)
            while (ld_acq(&d_cnt[l + 2]) < (unsigned)(GRP * (t - DD + 1))) {}
        if (tid == 1 && t > 0)
            while (ld_acq(&d_cnt[l + 1]) < (unsigned)(GRP * t)) {}
        if (tid == 2 && l > 0)
            while (ld_acq(&d_cnt[l]) < (unsigned)(GRP * (t + 1))) {}
        __syncthreads();

        const char* xb = xring + (size_t)((l == 0) ? t : (t & 7)) * 131072;
        const char* hb = myring + (size_t)((t - 1) & 7) * 131072;

#define STREAM(kc) do { unsigned int sb_ = smb + P_STR + ((kc) % 3) * STRB;           \
        int t2_ = tid & 255;                                                          \
        if (tid < 256) {                                                              \
            cp16(sb_ + t2_ * 16,         wab + 65536  + (kc) * 4096 + t2_ * 16);      \
            cp16(sb_ + 8192 + t2_ * 16,  xb + (kc) * 4096 + t2_ * 16);                \
            if (t > 0) cp16(sb_ + 16384 + t2_ * 16, hb + (kc) * 4096 + t2_ * 16);     \
        } else {                                                                      \
            cp16(sb_ + 4096  + t2_ * 16, wab + 196608 + (kc) * 4096 + t2_ * 16);      \
            cp16(sb_ + 12288 + t2_ * 16, xb + 65536 + (kc) * 4096 + t2_ * 16);        \
            if (t > 0) cp16(sb_ + 20480 + t2_ * 16, hb + 65536 + (kc) * 4096 + t2_ * 16); \
        }                                                                             \
        cp_commit(); } while (0)

        float wi[32], wh[32];
#pragma unroll
        for (int i = 0; i < 32; i++) { wi[i] = 0.f; wh[i] = 0.f; }

        STREAM(0); STREAM(1);
#pragma unroll 1
        for (int kc = 0; kc < 16; kc++) {
            if (kc < 15) cp_wait<1>(); else cp_wait<0>();
            __syncthreads();
            if (kc < 14) STREAM(kc + 2);
            const char* sbp = sm + P_STR + (kc % 3) * STRB;
            uint4 aWiH = *(const uint4*)(sm + P_WI + ((kc * 8 + wm) * 32 + lane) * 16);
            uint4 aWhH = *(const uint4*)(sm + P_WH + ((kc * 8 + wm) * 32 + lane) * 16);
            uint4 aWiL = *(const uint4*)(sbp + (wm * 32 + lane) * 16);
            uint4 aWhL = *(const uint4*)(sbp + 4096 + (wm * 32 + lane) * 16);
            bool doWi = (l > 0) || (kc < 5);
#pragma unroll
            for (int nb = 0; nb < 8; nb++) {
                int nblk = wn * 8 + nb;
                if (doWi) {
                    uint2 bXH = *(const uint2*)(sbp + 8192 + (nblk * 32 + lane) * 8);
                    uint2 bXL = *(const uint2*)(sbp + 12288 + (nblk * 32 + lane) * 8);
                    mma16816(wi + nb * 4, &aWiH.x, &bXH.x);
                    mma16816(wi + nb * 4, &aWiH.x, &bXL.x);
                    mma16816(wi + nb * 4, &aWiL.x, &bXH.x);
                }
                if (t > 0) {
                    uint2 bHH = *(const uint2*)(sbp + 16384 + (nblk * 32 + lane) * 8);
                    uint2 bHL = *(const uint2*)(sbp + 20480 + (nblk * 32 + lane) * 8);
                    mma16816(wh + nb * 4, &aWhH.x, &bHH.x);
                    mma16816(wh + nb * 4, &aWhH.x, &bHL.x);
                    mma16816(wh + nb * 4, &aWhL.x, &bHH.x);
                }
            }
        }
#undef STREAM

        // ---- per-warp partial BN stats over this warp's 64 batches ----
        float sl = 0, ql = 0, sh = 0, qh = 0;   // wi side, rows lo/hi
        float tl = 0, rl = 0, th = 0, rh = 0;   // wh side
#pragma unroll
        for (int nb = 0; nb < 8; nb++) {
            sl += wi[nb*4+0] + wi[nb*4+1];
            ql += wi[nb*4+0]*wi[nb*4+0] + wi[nb*4+1]*wi[nb*4+1];
            sh += wi[nb*4+2] + wi[nb*4+3];
            qh += wi[nb*4+2]*wi[nb*4+2] + wi[nb*4+3]*wi[nb*4+3];
            tl += wh[nb*4+0] + wh[nb*4+1];
            rl += wh[nb*4+0]*wh[nb*4+0] + wh[nb*4+1]*wh[nb*4+1];
            th += wh[nb*4+2] + wh[nb*4+3];
            rh += wh[nb*4+2]*wh[nb*4+2] + wh[nb*4+3]*wh[nb*4+3];
        }
#pragma unroll
        for (int o = 1; o <= 2; o <<= 1) {
            sl += __shfl_xor_sync(0xffffffffu, sl, o);
            ql += __shfl_xor_sync(0xffffffffu, ql, o);
            sh += __shfl_xor_sync(0xffffffffu, sh, o);
            qh += __shfl_xor_sync(0xffffffffu, qh, o);
            tl += __shfl_xor_sync(0xffffffffu, tl, o);
            rl += __shfl_xor_sync(0xffffffffu, rl, o);
            th += __shfl_xor_sync(0xffffffffu, th, o);
            rh += __shfl_xor_sync(0xffffffffu, rh, o);
        }
        if ((lane & 3) == 0) {
            float* rp = red + (w * 8 + (lane >> 2)) * 8;
            rp[0] = sl; rp[1] = ql; rp[2] = sh; rp[3] = qh;
            rp[4] = tl; rp[5] = rl; rp[6] = th; rp[7] = rh;
        }
        __syncthreads();

        // ---- combine halves, compute per-row BN coefficients ----
        float ai_lo, ai_hi, ah_lo, ah_hi, bs_lo, bs_hi;
        {
            int r = lane >> 2;
            const float* rp0 = red + ((wm)     * 8 + r) * 8;
            const float* rp1 = red + ((wm + 8) * 8 + r) * 8;
            float Sl = rp0[0] + rp1[0], Ql = rp0[1] + rp1[1];
            float Sh = rp0[2] + rp1[2], Qh = rp0[3] + rp1[3];
            float Tl = rp0[4] + rp1[4], Rl = rp0[5] + rp1[5];
            float Th = rp0[6] + rp1[6], Rh = rp0[7] + rp1[7];
            int jlo = wm * 16 + r, jhi = jlo + 8;
            float m = Sl * (1.f/128.f);
            ai_lo = prm[jlo] * rsqrtf(Ql * (1.f/128.f) - m * m + EPSV);
            bs_lo = prm[128 + jlo] - m * ai_lo;
            m = Sh * (1.f/128.f);
            ai_hi = prm[jhi] * rsqrtf(Qh * (1.f/128.f) - m * m + EPSV);
            bs_hi = prm[128 + jhi] - m * ai_hi;
            if (t > 0) {
                m = Tl * (1.f/128.f);
                ah_lo = prm[256 + jlo] * rsqrtf(Rl * (1.f/128.f) - m * m + EPSV);
                bs_lo += prm[384 + jlo] - m * ah_lo;
                m = Th * (1.f/128.f);
                ah_hi = prm[256 + jhi] * rsqrtf(Rh * (1.f/128.f) - m * m + EPSV);
                bs_hi += prm[384 + jhi] - m * ah_hi;
            } else {
                ah_lo = 0.f; ah_hi = 0.f;
                bs_lo += prm[384 + jlo]; bs_hi += prm[384 + jhi];
            }
        }

        // ---- single pass: s -> SMEM (stream bufs drained: sg alias safe) ----
        {
            const int c2 = 2 * (lane & 3);
            const int jl = wm * 16 + (lane >> 2);
#pragma unroll
            for (int nb = 0; nb < 8; nb++) {
                int bb = wn * 64 + nb * 8 + c2;
                sg[(bb+0) * 132 + jl]     = ai_lo * wi[nb*4+0] + ah_lo * wh[nb*4+0] + bs_lo;
                sg[(bb+1) * 132 + jl]     = ai_lo * wi[nb*4+1] + ah_lo * wh[nb*4+1] + bs_lo;
                sg[(bb+0) * 132 + jl + 8] = ai_hi * wi[nb*4+2] + ah_hi * wh[nb*4+2] + bs_hi;
                sg[(bb+1) * 132 + jl + 8] = ai_hi * wi[nb*4+3] + ah_hi * wh[nb*4+3] + bs_hi;
            }
        }
        __syncthreads();

        // ---- gates: thread (hc 0..31, bq 0..15) handles 8 batches ----
        float og[8];
#pragma unroll
        for (int i = 0; i < 8; i++) {
            float4 sv = *(const float4*)&sg[(i * 16 + bq) * 132 + hc * 4];
            float fg = fsigm(sv.x), ig = fsigm(sv.y);
            og[i] = fsigm(sv.z);
            cr[i] = fg * cr[i] + ig * ftanh(sv.w);
        }

        // ---- BN(c) over batch (16-lane groups share hc) ----
        float cs = 0.f, cq = 0.f;
#pragma unroll
        for (int i = 0; i < 8; i++) { cs += cr[i]; cq += cr[i] * cr[i]; }
#pragma unroll
        for (int o = 1; o <= 8; o <<= 1) {
            cs += __shfl_xor_sync(0xffffffffu, cs, o);
            cq += __shfl_xor_sync(0xffffffffu, cq, o);
        }
        float mc = cs * (1.f/128.f);
        float vc = cq * (1.f/128.f) - mc * mc;
        float rc = rsqrtf(vc + EPSV);
        float ac = prm[512 + hc] * rc, bc_ = prm[544 + hc] - mc * ac;
        __syncthreads();   // sg reads done -> reuse as h staging

        // ---- h, bf16 hi/lo, stage in fragment layout ----
#pragma unroll
        for (int i = 0; i < 8; i++) {
            float h = og[i] * ftanh(ac * cr[i] + bc_);
            __nv_bfloat16 hhi = __float2bfloat16(h);
            __nv_bfloat16 hlo = __float2bfloat16(h - __bfloat162float(hhi));
            int off = ((hc >> 4) * 4096)
                    + ((2 * i + (bq >> 3)) * 256)
                    + ((bq & 7) * 32) + (((hc & 7) >> 1) * 8)
                    + (((hc >> 3) & 1) * 4) + ((hc & 1) * 2);
            *(__nv_bfloat16*)(hst + off) = hhi;
            *(__nv_bfloat16*)(hst + 8192 + off) = hlo;
        }
        __syncthreads();
        {
            char* slot = myring + (size_t)(t & 7) * 131072;
#pragma unroll
            for (int it = 0; it < 2; it++) {
                int idx = it * 512 + tid;
                int part = idx >> 9, r = idx & 511;
                int kbl = r >> 8, rest = r & 255;
                *(uint4*)(slot + part * 65536 + (rank * 2 + kbl) * 4096 + rest * 16)
                    = *(const uint4*)(hst + part * 8192 + kbl * 4096 + rest * 16);
            }
        }
        // barrier orders all threads' h writes before tid0's release-arrive
        __syncthreads();
        if (tid == 0) arrive_rel(&d_cnt[l + 1]);
    }
}

// ================= final head =================
__launch_bounds__(256) __global__ void final_kernel(
    const float* __restrict__ Wlin, const float* __restrict__ blin,
    float* __restrict__ out)
{
    __shared__ float xr[256];
    __shared__ float lg[CC];
    __shared__ float rbuf[8];
    const char* img = (const char*)d_hB
        + (size_t)((LL - 1) * DD + ((TT - 1) & 7)) * 131072;
    int tid = threadIdx.x, warp = tid >> 5, lane = tid & 31;
    int b = blockIdx.x;
    {
        int off = boff(tid, b);
        float hi = __bfloat162float(*(const __nv_bfloat16*)(img + off));
        float lo = __bfloat162float(*(const __nv_bfloat16*)(img + 65536 + off));
        xr[tid] = hi + lo;
    }
    __syncthreads();

    float lmax = -1e30f;
    for (int cidx = tid; cidx < CC; cidx += 256) {
        float a = blin[cidx];
#pragma unroll 4
        for (int k = 0; k < 256; k++) a += xr[k] * Wlin[k * CC + cidx];
        lg[cidx] = a;
        lmax = fmaxf(lmax, a);
    }
#pragma unroll
    for (int o = 16; o; o >>= 1) lmax = fmaxf(lmax, __shfl_xor_sync(0xffffffffu, lmax, o));
    if (lane == 0) rbuf[warp] = lmax;
    __syncthreads();
    float M = rbuf[0];
#pragma unroll
    for (int w2 = 1; w2 < 8; w2++) M = fmaxf(M, rbuf[w2]);
    __syncthreads();
    float lsum = 0.f;
    for (int cidx = tid; cidx < CC; cidx += 256) {
        float e = __expf(lg[cidx] - M);
        lg[cidx] = e;
        lsum += e;
    }
#pragma unroll
    for (int o = 16; o; o >>= 1) lsum += __shfl_xor_sync(0xffffffffu, lsum, o);
    if (lane == 0) rbuf[warp] = lsum;
    __syncthreads();
    float S = 0.f;
#pragma unroll
    for (int w2 = 0; w2 < 8; w2++) S += rbuf[w2];
    float inv = 1.f / S;
    for (int cidx = tid; cidx < CC; cidx += 256)
        out[b * CC + cidx] = lg[cidx] * inv;
}

// ================= launch =================
extern "C" void kernel_launch(void* const* d_in, const int* in_sizes, int n_in,
                              void* d_out, int out_size)
{
    const float* seq  = (const float*)d_in[0];
    const float* Wih0 = (const float*)d_in[1];
    const float* Wih  = (const float*)d_in[2];
    const float* Whh  = (const float*)d_in[3];
    const float* bias = (const float*)d_in[4];
    const float* gih  = (const float*)d_in[5];
    const float* bih  = (const float*)d_in[6];
    const float* ghh  = (const float*)d_in[7];
    const float* bhh  = (const float*)d_in[8];
    const float* gc   = (const float*)d_in[9];
    const float* bc   = (const float*)d_in[10];
    const float* Wlin = (const float*)d_in[11];
    const float* blin = (const float*)d_in[12];
    float* out = (float*)d_out;

    cudaFuncSetAttribute((const void*)wave_kernel,
                         cudaFuncAttributeMaxDynamicSharedMemorySize, SMEM_TOT);

    prep_reset<<<1, 32>>>();
    prep_xseq<<<TT, 256>>>(seq);
    prep_w<<<dim3(LL, GRP), 256>>>(Wih0, Wih, Whh);
    wave_kernel<<<LL * GRP, 512, SMEM_TOT>>>(gih, bih, ghh, bhh, bias, gc, bc);
    final_kernel<<<BB, 256>>>(Wlin, blin, out);
}